// round 3
// baseline (speedup 1.0000x reference)
#include <cuda_runtime.h>

#define NN   2048
#define CDIM 256      // K*D
#define KCH  8
#define TN   32       // n-tile per block
#define TMT  32       // m-tile
#define MS   4        // m splits across grid.y
#define ZS   260      // padded smem row stride (floats)

typedef unsigned long long ull;

__device__ float    g_Z[2][NN * CDIM];       // ping-pong Z, [n][k*32+d]
__device__ float    g_part[MS][NN * CDIM];   // per-m-split partial aggregates
__device__ unsigned g_maskT[NN * (NN / 32)]; // transposed mask bits: word[m*64+nw], bit i = adj[nw*32+i][m]

// ---------- f32x2 helpers ----------
__device__ __forceinline__ void fma2(ull& d, ull a, ull b) {
    asm("fma.rn.f32x2 %0, %1, %2, %0;" : "+l"(d) : "l"(a), "l"(b));
}
__device__ __forceinline__ ull pk(float x, float y) {
    ull r; asm("mov.b64 %0, {%1, %2};" : "=l"(r) : "f"(x), "f"(y)); return r;
}
__device__ __forceinline__ ull bc2(float x) {
    ull r; asm("mov.b64 %0, {%1, %1};" : "=l"(r) : "f"(x)); return r;
}
__device__ __forceinline__ float2 up2(ull v) {
    float2 r; asm("mov.b64 {%0, %1}, %2;" : "=f"(r.x), "=f"(r.y) : "l"(v)); return r;
}

// ---------------- transposed mask pack ----------------
__global__ void pack_maskT_kernel(const int* __restrict__ adj) {
    int nw = blockIdx.x;                       // 0..63
    int m  = blockIdx.y * 256 + threadIdx.x;   // 0..2047
    unsigned bits = 0;
#pragma unroll 8
    for (int i = 0; i < 32; i++)
        bits |= (adj[(size_t)(nw * 32 + i) * NN + m] > 0 ? 1u : 0u) << i;
    g_maskT[m * 64 + nw] = bits;
}

// ---------------- projection + L2 norm -> g_Z[0] ----------------
__global__ void proj_kernel(const float* __restrict__ feat,
                            const float* __restrict__ W,
                            const float* __restrict__ b) {
    __shared__ float fs[128];
    int n = blockIdx.x, t = threadIdx.x;
    if (t < 128) fs[t] = feat[n * 128 + t];
    __syncthreads();
    int k = t >> 5, d = t & 31;
    const float* Wp = W + k * 4096 + d;
    float s = b[t];
#pragma unroll 16
    for (int i = 0; i < 128; i++) s = fmaf(fs[i], Wp[i * 32], s);
    float ss = s * s;
#pragma unroll
    for (int o = 16; o; o >>= 1) ss += __shfl_xor_sync(0xffffffffu, ss, o);
    float inv = 1.0f / fmaxf(sqrtf(ss), 1e-12f);
    g_Z[0][(size_t)n * CDIM + t] = s * inv;
}

// ---------------- fused scores + channel-softmax + aggregation ----------------
// grid (NN/TN, MS), 256 threads, 2 blocks/SM.
__global__ __launch_bounds__(256, 2) void iter_kernel(int zi) {
    extern __shared__ char smem_raw[];
    float (*Zn_s)[ZS]        = (float(*)[ZS])(smem_raw);
    float (*Zm_s)[ZS]        = (float(*)[ZS])(smem_raw + TN * ZS * 4);
    float (*att_s)[TMT][TN]  = (float(*)[TMT][TN])(smem_raw + 2 * TN * ZS * 4); // [k][m][n]

    const float* __restrict__ Z = g_Z[zi];
    int t     = threadIdx.x;
    int n0    = blockIdx.x * TN;
    int mbase = blockIdx.y * (NN / MS);

    // load Zn tile (TN x 256)
    {
        const float4* src = (const float4*)(Z + (size_t)n0 * CDIM);
#pragma unroll
        for (int j = 0; j < 8; j++) {
            int idx = t + j * 256;
            *(float4*)&Zn_s[idx >> 6][(idx & 63) * 4] = src[idx];
        }
    }

    // Phase A mapping: 4 channel-groups of 64 threads; 8x8 thread grid; 4x4 pair tile
    int ch0 = t >> 6;            // 0..3 (channels ch0 and ch0+4)
    int tyy = (t & 63) >> 3;     // 0..7 -> m rows {tyy+8i}
    int txx = t & 7;             // 0..7 -> n cols {txx+8j}
    // Phase B mapping: warp = channel, lane = dim
    int kb = t >> 5, d = t & 31;

    ull acc2[16];                // 32 n-values packed in pairs, fixed (kb, d)
#pragma unroll
    for (int q = 0; q < 16; q++) acc2[q] = 0ull;

    const int NTILES = (NN / MS) / TMT;
    for (int mt = 0; mt < NTILES; mt++) {
        int m0 = mbase + mt * TMT;
        __syncthreads();
        {
            const float4* src = (const float4*)(Z + (size_t)m0 * CDIM);
#pragma unroll
            for (int j = 0; j < 8; j++) {
                int idx = t + j * 256;
                *(float4*)&Zm_s[idx >> 6][(idx & 63) * 4] = src[idx];
            }
        }
        __syncthreads();

        // ---- Phase A: raw scores -> att_s[ch][m][n] (f32x2 GEMM-let, 4x4/thread) ----
#pragma unroll
        for (int cc = 0; cc < 2; cc++) {
            int ch = ch0 + cc * 4;
            ull sacc[16];
#pragma unroll
            for (int q = 0; q < 16; q++) sacc[q] = 0ull;
#pragma unroll
            for (int s2 = 0; s2 < 8; s2++) {     // 4 dims per step
                ull a0[4], a1[4], b0[4], b1[4];
#pragma unroll
                for (int j = 0; j < 4; j++) {
                    float4 v = *(const float4*)&Zn_s[txx + 8 * j][ch * 32 + 4 * s2];
                    a0[j] = pk(v.x, v.y); a1[j] = pk(v.z, v.w);
                }
#pragma unroll
                for (int i = 0; i < 4; i++) {
                    float4 v = *(const float4*)&Zm_s[tyy + 8 * i][ch * 32 + 4 * s2];
                    b0[i] = pk(v.x, v.y); b1[i] = pk(v.z, v.w);
                }
#pragma unroll
                for (int i = 0; i < 4; i++)
#pragma unroll
                    for (int j = 0; j < 4; j++) {
                        fma2(sacc[i * 4 + j], a0[j], b0[i]);
                        fma2(sacc[i * 4 + j], a1[j], b1[i]);
                    }
            }
#pragma unroll
            for (int i = 0; i < 4; i++)
#pragma unroll
                for (int j = 0; j < 4; j++) {
                    float2 v = up2(sacc[i * 4 + j]);
                    att_s[ch][tyy + 8 * i][txx + 8 * j] = v.x + v.y;
                }
        }
        __syncthreads();

        // ---- Phase S: softmax over channels, in place; mask from g_maskT ----
        {
            int ml = t >> 3;            // 0..31
            int nb = (t & 7) * 4;       // n group of 4
            float4 e[8];
            float4 sum = make_float4(0.f, 0.f, 0.f, 0.f);
#pragma unroll
            for (int k = 0; k < 8; k++) {
                float4 v = *(const float4*)&att_s[k][ml][nb];
                // |score| <= 1 (unit rows): softmax safe without max subtraction
                e[k].x = __expf(v.x); e[k].y = __expf(v.y);
                e[k].z = __expf(v.z); e[k].w = __expf(v.w);
                sum.x += e[k].x; sum.y += e[k].y; sum.z += e[k].z; sum.w += e[k].w;
            }
            unsigned wb = g_maskT[(size_t)(m0 + ml) * 64 + (n0 >> 5)] >> nb;
            float4 inv;
            inv.x = (wb & 1u)        ? __fdividef(1.f, sum.x) : 0.f;
            inv.y = ((wb >> 1) & 1u) ? __fdividef(1.f, sum.y) : 0.f;
            inv.z = ((wb >> 2) & 1u) ? __fdividef(1.f, sum.z) : 0.f;
            inv.w = ((wb >> 3) & 1u) ? __fdividef(1.f, sum.w) : 0.f;
#pragma unroll
            for (int k = 0; k < 8; k++) {
                float4 o;
                o.x = e[k].x * inv.x; o.y = e[k].y * inv.y;
                o.z = e[k].z * inv.z; o.w = e[k].w * inv.w;
                *(float4*)&att_s[k][ml][nb] = o;
            }
        }
        __syncthreads();

        // ---- Phase B: acc[n(pair),d] += att[kb][m][n] * Z[kb][m][d]  (f32x2) ----
#pragma unroll 4
        for (int m = 0; m < 32; m++) {
            ull z2 = bc2(Zm_s[m][kb * 32 + d]);
            const float4* arow = (const float4*)&att_s[kb][m][0];
#pragma unroll
            for (int q = 0; q < 8; q++) {
                float4 a = arow[q];              // broadcast LDS.128
                fma2(acc2[2 * q],     pk(a.x, a.y), z2);
                fma2(acc2[2 * q + 1], pk(a.z, a.w), z2);
            }
        }
    }

    float* dst = g_part[blockIdx.y];
#pragma unroll
    for (int q = 0; q < 16; q++) {
        float2 v = up2(acc2[q]);
        dst[(size_t)(n0 + 2 * q) * CDIM + kb * 32 + d]     = v.x;
        dst[(size_t)(n0 + 2 * q + 1) * CDIM + kb * 32 + d] = v.y;
    }
}

// ---------------- residual + sum partials + L2 norm ----------------
__global__ void norm_kernel(int zi, int zo, float* __restrict__ outp) {
    int n = blockIdx.x, t = threadIdx.x;
    size_t i = (size_t)n * CDIM + t;
    float v = g_Z[zi][i] + g_part[0][i] + g_part[1][i] + g_part[2][i] + g_part[3][i];
    float ss = v * v;
#pragma unroll
    for (int o = 16; o; o >>= 1) ss += __shfl_xor_sync(0xffffffffu, ss, o);
    float r = v / fmaxf(sqrtf(ss), 1e-12f);
    if (outp) outp[i] = r; else g_Z[zo][i] = r;
}

extern "C" void kernel_launch(void* const* d_in, const int* in_sizes, int n_in,
                              void* d_out, int out_size) {
    const int* adj = nullptr; const float* feat = nullptr;
    const float* W = nullptr; const float* b = nullptr;
    for (int i = 0; i < n_in; i++) {
        switch (in_sizes[i]) {
            case NN * NN:      adj  = (const int*)d_in[i];   break;
            case NN * 128:     feat = (const float*)d_in[i]; break;
            case 8 * 128 * 32: W    = (const float*)d_in[i]; break;
            case 256:          b    = (const float*)d_in[i]; break;
        }
    }
    float* out = (float*)d_out;

    const int SMEM = (2 * TN * ZS + KCH * TN * TMT) * 4;   // 99328 bytes
    cudaFuncSetAttribute(iter_kernel, cudaFuncAttributeMaxDynamicSharedMemorySize, SMEM);

    pack_maskT_kernel<<<dim3(64, 8), 256>>>(adj);
    proj_kernel<<<NN, 256>>>(feat, W, b);

    int cur = 0;
    for (int it = 0; it < 4; it++) {
        dim3 grid(NN / TN, MS);
        iter_kernel<<<grid, 256, SMEM>>>(cur);
        norm_kernel<<<NN, 256>>>(cur, cur ^ 1, (it == 3) ? out : nullptr);
        cur ^= 1;
    }
}

// round 6
// speedup vs baseline: 1.7600x; 1.7600x over previous
#include <cuda_runtime.h>
#include <cuda_bf16.h>
#include <cstdint>

#define NN   2048
#define CDIM 256
#define MS   8          // m splits (blockIdx.y)
#define PAD  264        // bf16 elems per smem row (padded)

__device__ float    g_Z[2][NN * CDIM];
__device__ float    g_part[2 * MS][NN * CDIM];   // per (msplit, m-half) partials
__device__ unsigned g_maskbits[NN * (NN / 32)];  // word[n*64+mw], bit = m&31

// smem byte offsets (all 16B aligned)
#define OFF_ZNH 0
#define OFF_ZNL (64 * PAD * 2)            // 33792
#define OFF_ZMH (2 * 64 * PAD * 2)        // 67584
#define OFF_ZML (OFF_ZMH + 32 * PAD * 2)  // 84480
#define SM_TOTAL (OFF_ZML + 32 * PAD * 2) // 101376

__device__ __forceinline__ uint32_t smem_u32(const void* p) {
    uint32_t a;
    asm("{ .reg .u64 t; cvta.to.shared.u64 t, %1; cvt.u32.u64 %0, t; }" : "=r"(a) : "l"(p));
    return a;
}

// float pair -> bf16 high/low split, packed as b32 (elem0 in low half)
__device__ __forceinline__ void splitpair(float x0, float x1, uint32_t& h, uint32_t& l) {
    __nv_bfloat16 h0 = __float2bfloat16(x0), h1 = __float2bfloat16(x1);
    float r0 = x0 - __bfloat162float(h0), r1 = x1 - __bfloat162float(h1);
    __nv_bfloat162 hp; hp.x = h0; hp.y = h1;
    __nv_bfloat162 lp; lp.x = __float2bfloat16(r0); lp.y = __float2bfloat16(r1);
    h = *(uint32_t*)&hp; l = *(uint32_t*)&lp;
}

#define LDSM4(r, a) asm volatile( \
    "ldmatrix.sync.aligned.m8n8.x4.shared.b16 {%0,%1,%2,%3}, [%4];" \
    : "=r"((r)[0]), "=r"((r)[1]), "=r"((r)[2]), "=r"((r)[3]) : "r"(a))
#define LDSM4T(r, a) asm volatile( \
    "ldmatrix.sync.aligned.m8n8.x4.trans.shared.b16 {%0,%1,%2,%3}, [%4];" \
    : "=r"((r)[0]), "=r"((r)[1]), "=r"((r)[2]), "=r"((r)[3]) : "r"(a))
#define MMA(d, a, b0, b1) asm volatile( \
    "mma.sync.aligned.m16n8k16.row.col.f32.bf16.bf16.f32 " \
    "{%0,%1,%2,%3}, {%4,%5,%6,%7}, {%8,%9}, {%0,%1,%2,%3};" \
    : "+f"((d)[0]), "+f"((d)[1]), "+f"((d)[2]), "+f"((d)[3]) \
    : "r"((a)[0]), "r"((a)[1]), "r"((a)[2]), "r"((a)[3]), "r"(b0), "r"(b1))

// ---------------- pack adjacency bits [n][mword] ----------------
__global__ void pack_mask_kernel(const int* __restrict__ adj) {
    int wIdx = blockIdx.x * 256 + threadIdx.x;
    const int4* p = ((const int4*)adj) + (size_t)wIdx * 8;
    unsigned bits = 0;
#pragma unroll
    for (int j = 0; j < 8; j++) {
        int4 v = p[j];
        if (v.x > 0) bits |= 1u << (4 * j + 0);
        if (v.y > 0) bits |= 1u << (4 * j + 1);
        if (v.z > 0) bits |= 1u << (4 * j + 2);
        if (v.w > 0) bits |= 1u << (4 * j + 3);
    }
    g_maskbits[wIdx] = bits;
}

// ---------------- projection + L2 norm ----------------
__global__ void proj_kernel(const float* __restrict__ feat,
                            const float* __restrict__ W,
                            const float* __restrict__ b) {
    __shared__ float fs[128];
    int n = blockIdx.x, t = threadIdx.x;
    if (t < 128) fs[t] = feat[n * 128 + t];
    __syncthreads();
    int k = t >> 5, d = t & 31;
    const float* Wp = W + k * 4096 + d;
    float s = b[t];
#pragma unroll 16
    for (int i = 0; i < 128; i++) s = fmaf(fs[i], Wp[i * 32], s);
    float ss = s * s;
#pragma unroll
    for (int o = 16; o; o >>= 1) ss += __shfl_xor_sync(0xffffffffu, ss, o);
    float inv = 1.0f / fmaxf(sqrtf(ss), 1e-12f);
    g_Z[0][(size_t)n * CDIM + t] = s * inv;
}

// ---------------- fused iteration: mma.sync bf16 3-term split ----------------
// block: 64 n-rows x 256 m-cols; 8 warps = 4 n-blocks(16) x 2 m-halves(16)
__global__ __launch_bounds__(256, 1) void iter_kernel(int zi) {
    extern __shared__ char smem[];
    const float* __restrict__ Z = g_Z[zi];
    uint32_t sb = smem_u32(smem);
    int t = threadIdx.x, w = t >> 5, lane = t & 31;
    int nb = w & 3, mh = w >> 2;
    int g = lane >> 2, tig = lane & 3;
    int n0 = blockIdx.x * 64, mbase = blockIdx.y * (NN / MS);

    // ---- fill Zn (64 x 256) split bf16 h/l ----
#pragma unroll 4
    for (int it = 0; it < 32; it++) {
        int idx = t + it * 256;              // float2 index over 8192
        int n = idx >> 7, cp = idx & 127;
        float2 v = *(const float2*)(Z + (size_t)(n0 + n) * CDIM + 2 * cp);
        uint32_t h, l; splitpair(v.x, v.y, h, l);
        uint32_t bo = (uint32_t)(n * PAD + 2 * cp) * 2;
        *(uint32_t*)(smem + OFF_ZNH + bo) = h;
        *(uint32_t*)(smem + OFF_ZNL + bo) = l;
    }
    __syncthreads();

    // per-lane ldmatrix base offsets (bytes)
    uint32_t aoffA = (uint32_t)(((nb * 16 + (lane & 15)) * PAD + ((lane >> 4) << 3)) * 2);
    uint32_t boffA = (uint32_t)(((mh * 16 + ((lane >> 4) << 3) + (lane & 7)) * PAD +
                                 (((lane >> 3) & 1) << 3)) * 2);
    uint32_t boffT = (uint32_t)(((mh * 16 + (((lane >> 3) & 1) << 3) + (lane & 7)) * PAD +
                                 ((lane >> 4) << 3)) * 2);

    int nA = n0 + nb * 16 + g;               // lane's first n row; +8 for second

    float C[8][4][4];                        // [ch][dblock][frag] persistent
#pragma unroll
    for (int c = 0; c < 8; c++)
#pragma unroll
        for (int q = 0; q < 4; q++) { C[c][q][0] = C[c][q][1] = C[c][q][2] = C[c][q][3] = 0.f; }

    for (int mt = 0; mt < 8; mt++) {
        int m0 = mbase + mt * 32;
        if (mt) __syncthreads();
        // ---- fill Zm (32 x 256) split bf16 ----
#pragma unroll 2
        for (int it = 0; it < 16; it++) {
            int idx = t + it * 256;          // float2 index over 4096
            int m = idx >> 7, cp = idx & 127;
            float2 v = *(const float2*)(Z + (size_t)(m0 + m) * CDIM + 2 * cp);
            uint32_t h, l; splitpair(v.x, v.y, h, l);
            uint32_t bo = (uint32_t)(m * PAD + 2 * cp) * 2;
            *(uint32_t*)(smem + OFF_ZMH + bo) = h;
            *(uint32_t*)(smem + OFF_ZML + bo) = l;
        }
        __syncthreads();

        // ---- Phase A: S[ch][msub][4] = Zn . Zm^T, 3-term split ----
        float S[8][2][4];
#pragma unroll
        for (int c = 0; c < 8; c++)
#pragma unroll
            for (int ms = 0; ms < 2; ms++) { S[c][ms][0] = S[c][ms][1] = S[c][ms][2] = S[c][ms][3] = 0.f; }
#pragma unroll
        for (int ch = 0; ch < 8; ch++) {
#pragma unroll
            for (int ks = 0; ks < 2; ks++) {
                uint32_t kb2 = (uint32_t)(ch * 32 + ks * 16) * 2;
                uint32_t aH[4], aL[4], bH[4], bL[4];
                LDSM4(aH, sb + OFF_ZNH + aoffA + kb2);
                LDSM4(aL, sb + OFF_ZNL + aoffA + kb2);
                LDSM4(bH, sb + OFF_ZMH + boffA + kb2);
                LDSM4(bL, sb + OFF_ZML + boffA + kb2);
                MMA(S[ch][0], aH, bH[0], bH[1]); MMA(S[ch][1], aH, bH[2], bH[3]);
                MMA(S[ch][0], aL, bH[0], bH[1]); MMA(S[ch][1], aL, bH[2], bH[3]);
                MMA(S[ch][0], aH, bL[0], bL[1]); MMA(S[ch][1], aH, bL[2], bL[3]);
            }
        }

        // ---- softmax over channels (all in-lane) ----
        float sum[2][4];
#pragma unroll
        for (int ms = 0; ms < 2; ms++)
#pragma unroll
            for (int q = 0; q < 4; q++) sum[ms][q] = 0.f;
#pragma unroll
        for (int ch = 0; ch < 8; ch++)
#pragma unroll
            for (int ms = 0; ms < 2; ms++)
#pragma unroll
                for (int q = 0; q < 4; q++) {
                    float e = __expf(S[ch][ms][q]);   // |s|<=1: no max-sub needed
                    S[ch][ms][q] = e; sum[ms][q] += e;
                }
        unsigned wA = g_maskbits[(size_t)nA * 64 + (m0 >> 5)];
        unsigned wB = g_maskbits[(size_t)(nA + 8) * 64 + (m0 >> 5)];
        float inv[2][4];
#pragma unroll
        for (int ms = 0; ms < 2; ms++)
#pragma unroll
            for (int q = 0; q < 4; q++) {
                int bitpos = mh * 16 + ms * 8 + 2 * tig + (q & 1);
                unsigned wd = (q >> 1) ? wB : wA;
                inv[ms][q] = ((wd >> bitpos) & 1u) ? __fdividef(1.f, sum[ms][q]) : 0.f;
            }
        // att -> bf16 h/l fragments (a-frag order: [msub*2 + rowblock])
        uint32_t attH[8][4], attL[8][4];
#pragma unroll
        for (int ch = 0; ch < 8; ch++)
#pragma unroll
            for (int ms = 0; ms < 2; ms++) {
                splitpair(S[ch][ms][0] * inv[ms][0], S[ch][ms][1] * inv[ms][1],
                          attH[ch][ms * 2], attL[ch][ms * 2]);
                splitpair(S[ch][ms][2] * inv[ms][2], S[ch][ms][3] * inv[ms][3],
                          attH[ch][ms * 2 + 1], attL[ch][ms * 2 + 1]);
            }

        // ---- Phase B: C[ch] += att . Zm  (B via ldmatrix.trans), 3-term ----
#pragma unroll
        for (int ch = 0; ch < 8; ch++) {
            uint32_t d0 = (uint32_t)(ch * 32) * 2, d1 = (uint32_t)(ch * 32 + 16) * 2;
            uint32_t bh0[4], bh1[4], bl0[4], bl1[4];
            LDSM4T(bh0, sb + OFF_ZMH + boffT + d0);
            LDSM4T(bh1, sb + OFF_ZMH + boffT + d1);
            LDSM4T(bl0, sb + OFF_ZML + boffT + d0);
            LDSM4T(bl1, sb + OFF_ZML + boffT + d1);
            MMA(C[ch][0], attH[ch], bh0[0], bh0[1]);
            MMA(C[ch][1], attH[ch], bh0[2], bh0[3]);
            MMA(C[ch][2], attH[ch], bh1[0], bh1[1]);
            MMA(C[ch][3], attH[ch], bh1[2], bh1[3]);
            MMA(C[ch][0], attL[ch], bh0[0], bh0[1]);
            MMA(C[ch][1], attL[ch], bh0[2], bh0[3]);
            MMA(C[ch][2], attL[ch], bh1[0], bh1[1]);
            MMA(C[ch][3], attL[ch], bh1[2], bh1[3]);
            MMA(C[ch][0], attH[ch], bl0[0], bl0[1]);
            MMA(C[ch][1], attH[ch], bl0[2], bl0[3]);
            MMA(C[ch][2], attH[ch], bl1[0], bl1[1]);
            MMA(C[ch][3], attH[ch], bl1[2], bl1[3]);
        }
    }

    // ---- readout partial aggregates ----
    float* dst = g_part[blockIdx.y * 2 + mh];
#pragma unroll
    for (int ch = 0; ch < 8; ch++)
#pragma unroll
        for (int db = 0; db < 4; db++) {
            int d = ch * 32 + db * 8 + 2 * tig;
            *(float2*)&dst[(size_t)nA * CDIM + d]       = make_float2(C[ch][db][0], C[ch][db][1]);
            *(float2*)&dst[(size_t)(nA + 8) * CDIM + d] = make_float2(C[ch][db][2], C[ch][db][3]);
        }
}

// ---------------- residual + sum 16 partials + L2 norm ----------------
__global__ void norm_kernel(int zi, int zo, float* __restrict__ outp) {
    int n = blockIdx.x, t = threadIdx.x;
    size_t i = (size_t)n * CDIM + t;
    float v = g_Z[zi][i];
#pragma unroll
    for (int s = 0; s < 2 * MS; s++) v += g_part[s][i];
    float ss = v * v;
#pragma unroll
    for (int o = 16; o; o >>= 1) ss += __shfl_xor_sync(0xffffffffu, ss, o);
    float r = v / fmaxf(sqrtf(ss), 1e-12f);
    if (outp) outp[i] = r; else g_Z[zo][i] = r;
}

extern "C" void kernel_launch(void* const* d_in, const int* in_sizes, int n_in,
                              void* d_out, int out_size) {
    const int* adj = nullptr; const float* feat = nullptr;
    const float* W = nullptr; const float* b = nullptr;
    for (int i = 0; i < n_in; i++) {
        switch (in_sizes[i]) {
            case NN * NN:      adj  = (const int*)d_in[i];   break;
            case NN * 128:     feat = (const float*)d_in[i]; break;
            case 8 * 128 * 32: W    = (const float*)d_in[i]; break;
            case 256:          b    = (const float*)d_in[i]; break;
        }
    }
    float* out = (float*)d_out;

    cudaFuncSetAttribute(iter_kernel, cudaFuncAttributeMaxDynamicSharedMemorySize, SM_TOTAL);

    pack_mask_kernel<<<NN * (NN / 32) / 256, 256>>>(adj);
    proj_kernel<<<NN, 256>>>(feat, W, b);

    int cur = 0;
    for (int it = 0; it < 4; it++) {
        dim3 grid(NN / 64, MS);
        iter_kernel<<<grid, 256, SM_TOTAL>>>(cur);
        norm_kernel<<<NN, 256>>>(cur, cur ^ 1, (it == 3) ? out : nullptr);
        cur ^= 1;
    }
}

// round 8
// speedup vs baseline: 1.7976x; 1.0214x over previous
#include <cuda_runtime.h>
#include <cuda_bf16.h>
#include <cstdint>

#define NN   2048
#define CDIM 256
#define MS   8          // m splits (blockIdx.y)
#define PAD  264        // bf16 elems per smem row (padded)

__device__ float    g_Z[2][NN * CDIM];
__device__ float    g_part[MS][NN * CDIM];       // per m-split partials (halves combined)
__device__ unsigned g_maskbits[NN * (NN / 32)];  // word[n*64+mw], bit = m&31

// smem byte offsets
#define OFF_ZNH  0
#define OFF_ZNL  (64 * PAD * 2)                  // 33792
#define OFF_ZM   (2 * 64 * PAD * 2)              // 67584; 2 buffers of (h|l)
#define ZMBUF    (2 * 32 * PAD * 2)              // 33792 per buffer (h then l)
#define ZMHALF   (32 * PAD * 2)                  // 16896
#define SM_TOTAL (OFF_ZM + 2 * ZMBUF)            // 135168
#define CPAD     264                             // combine-area row stride (floats)

__device__ __forceinline__ uint32_t smem_u32(const void* p) {
    uint32_t a;
    asm("{ .reg .u64 t; cvta.to.shared.u64 t, %1; cvt.u32.u64 %0, t; }" : "=r"(a) : "l"(p));
    return a;
}

// float pair -> bf16 high/low split, packed b32 (elem0 low half)
__device__ __forceinline__ void splitpair(float x0, float x1, uint32_t& h, uint32_t& l) {
    __nv_bfloat16 h0 = __float2bfloat16(x0), h1 = __float2bfloat16(x1);
    float r0 = x0 - __bfloat162float(h0), r1 = x1 - __bfloat162float(h1);
    __nv_bfloat162 hp; hp.x = h0; hp.y = h1;
    __nv_bfloat162 lp; lp.x = __float2bfloat16(r0); lp.y = __float2bfloat16(r1);
    h = *(uint32_t*)&hp; l = *(uint32_t*)&lp;
}

#define LDSM4(r, a) asm volatile( \
    "ldmatrix.sync.aligned.m8n8.x4.shared.b16 {%0,%1,%2,%3}, [%4];" \
    : "=r"((r)[0]), "=r"((r)[1]), "=r"((r)[2]), "=r"((r)[3]) : "r"(a))
#define LDSM4T(r, a) asm volatile( \
    "ldmatrix.sync.aligned.m8n8.x4.trans.shared.b16 {%0,%1,%2,%3}, [%4];" \
    : "=r"((r)[0]), "=r"((r)[1]), "=r"((r)[2]), "=r"((r)[3]) : "r"(a))
#define MMA(d, a, b0, b1) asm volatile( \
    "mma.sync.aligned.m16n8k16.row.col.f32.bf16.bf16.f32 " \
    "{%0,%1,%2,%3}, {%4,%5,%6,%7}, {%8,%9}, {%0,%1,%2,%3};" \
    : "+f"((d)[0]), "+f"((d)[1]), "+f"((d)[2]), "+f"((d)[3]) \
    : "r"((a)[0]), "r"((a)[1]), "r"((a)[2]), "r"((a)[3]), "r"(b0), "r"(b1))

// ---------------- pack adjacency bits [n][mword] ----------------
__global__ void pack_mask_kernel(const int* __restrict__ adj) {
    int wIdx = blockIdx.x * 256 + threadIdx.x;
    const int4* p = ((const int4*)adj) + (size_t)wIdx * 8;
    unsigned bits = 0;
#pragma unroll
    for (int j = 0; j < 8; j++) {
        int4 v = p[j];
        if (v.x > 0) bits |= 1u << (4 * j + 0);
        if (v.y > 0) bits |= 1u << (4 * j + 1);
        if (v.z > 0) bits |= 1u << (4 * j + 2);
        if (v.w > 0) bits |= 1u << (4 * j + 3);
    }
    g_maskbits[wIdx] = bits;
}

// ---------------- projection + L2 norm ----------------
__global__ void proj_kernel(const float* __restrict__ feat,
                            const float* __restrict__ W,
                            const float* __restrict__ b) {
    __shared__ float fs[128];
    int n = blockIdx.x, t = threadIdx.x;
    if (t < 128) fs[t] = feat[n * 128 + t];
    __syncthreads();
    int k = t >> 5, d = t & 31;
    const float* Wp = W + k * 4096 + d;
    float s = b[t];
#pragma unroll 16
    for (int i = 0; i < 128; i++) s = fmaf(fs[i], Wp[i * 32], s);
    float ss = s * s;
#pragma unroll
    for (int o = 16; o; o >>= 1) ss += __shfl_xor_sync(0xffffffffu, ss, o);
    float inv = 1.0f / fmaxf(sqrtf(ss), 1e-12f);
    g_Z[0][(size_t)n * CDIM + t] = s * inv;
}

// ---------------- fused iteration ----------------
// block: 64 n x 256 m; 8 warps = 4 n-blocks(16) x 2 m-halves(128)
__global__ __launch_bounds__(256, 1) void iter_kernel(int zi) {
    extern __shared__ char smem[];
    const float* __restrict__ Z = g_Z[zi];
    uint32_t sb = smem_u32(smem);
    int t = threadIdx.x, w = t >> 5, lane = t & 31;
    int nb = w & 3, mh = w >> 2;
    int g = lane >> 2, tig = lane & 3;
    int n0 = blockIdx.x * 64, mbase = blockIdx.y * (NN / MS);

    // ---- fill Zn (64 x 256) split bf16 h/l ----
#pragma unroll 4
    for (int it = 0; it < 32; it++) {
        int idx = t + it * 256;
        int n = idx >> 7, cp = idx & 127;
        float2 v = *(const float2*)(Z + (size_t)(n0 + n) * CDIM + 2 * cp);
        uint32_t h, l; splitpair(v.x, v.y, h, l);
        uint32_t bo = (uint32_t)(n * PAD + 2 * cp) * 2;
        *(uint32_t*)(smem + OFF_ZNH + bo) = h;
        *(uint32_t*)(smem + OFF_ZNL + bo) = l;
    }

    // fill Zm tile 0 into buffer 0
    {
#pragma unroll 2
        for (int it = 0; it < 16; it++) {
            int idx = t + it * 256;
            int m = idx >> 7, cp = idx & 127;
            float2 v = *(const float2*)(Z + (size_t)(mbase + m) * CDIM + 2 * cp);
            uint32_t h, l; splitpair(v.x, v.y, h, l);
            uint32_t bo = (uint32_t)(m * PAD + 2 * cp) * 2;
            *(uint32_t*)(smem + OFF_ZM + bo) = h;
            *(uint32_t*)(smem + OFF_ZM + ZMHALF + bo) = l;
        }
    }
    __syncthreads();

    uint32_t aoffA = (uint32_t)(((nb * 16 + (lane & 15)) * PAD + ((lane >> 4) << 3)) * 2);
    uint32_t boffA = (uint32_t)(((mh * 16 + ((lane >> 4) << 3) + (lane & 7)) * PAD +
                                 (((lane >> 3) & 1) << 3)) * 2);
    uint32_t boffT = (uint32_t)(((mh * 16 + (((lane >> 3) & 1) << 3) + (lane & 7)) * PAD +
                                 ((lane >> 4) << 3)) * 2);
    int nA = n0 + nb * 16 + g;

    float C[8][4][4];
#pragma unroll
    for (int c = 0; c < 8; c++)
#pragma unroll
        for (int q = 0; q < 4; q++) { C[c][q][0] = C[c][q][1] = C[c][q][2] = C[c][q][3] = 0.f; }

    for (int mt = 0; mt < 8; mt++) {
        int m0 = mbase + mt * 32;
        uint32_t bufc = OFF_ZM + (uint32_t)(mt & 1) * ZMBUF;

        // ---- prefetch next Zm tile into other buffer (overlaps compute) ----
        if (mt < 7) {
            uint32_t bufn = OFF_ZM + (uint32_t)((mt + 1) & 1) * ZMBUF;
            int m1 = m0 + 32;
#pragma unroll 2
            for (int it = 0; it < 16; it++) {
                int idx = t + it * 256;
                int m = idx >> 7, cp = idx & 127;
                float2 v = *(const float2*)(Z + (size_t)(m1 + m) * CDIM + 2 * cp);
                uint32_t h, l; splitpair(v.x, v.y, h, l);
                uint32_t bo = (uint32_t)(m * PAD + 2 * cp) * 2;
                *(uint32_t*)(smem + bufn + bo) = h;
                *(uint32_t*)(smem + bufn + ZMHALF + bo) = l;
            }
        }

        // ---- Phase A: S = Zn . Zm^T (3-term split) ----
        float S[8][2][4];
#pragma unroll
        for (int c = 0; c < 8; c++)
#pragma unroll
            for (int ms = 0; ms < 2; ms++) { S[c][ms][0] = S[c][ms][1] = S[c][ms][2] = S[c][ms][3] = 0.f; }
#pragma unroll
        for (int ch = 0; ch < 8; ch++) {
#pragma unroll
            for (int ks = 0; ks < 2; ks++) {
                uint32_t kb2 = (uint32_t)(ch * 32 + ks * 16) * 2;
                uint32_t aH[4], aL[4], bH[4], bL[4];
                LDSM4(aH, sb + OFF_ZNH + aoffA + kb2);
                LDSM4(aL, sb + OFF_ZNL + aoffA + kb2);
                LDSM4(bH, sb + bufc + boffA + kb2);
                LDSM4(bL, sb + bufc + ZMHALF + boffA + kb2);
                MMA(S[ch][0], aH, bH[0], bH[1]); MMA(S[ch][1], aH, bH[2], bH[3]);
                MMA(S[ch][0], aL, bH[0], bH[1]); MMA(S[ch][1], aL, bH[2], bH[3]);
                MMA(S[ch][0], aH, bL[0], bL[1]); MMA(S[ch][1], aH, bL[2], bL[3]);
            }
        }

        // ---- softmax over channels (in-lane) ----
        float sum[2][4];
#pragma unroll
        for (int ms = 0; ms < 2; ms++)
#pragma unroll
            for (int q = 0; q < 4; q++) sum[ms][q] = 0.f;
#pragma unroll
        for (int ch = 0; ch < 8; ch++)
#pragma unroll
            for (int ms = 0; ms < 2; ms++)
#pragma unroll
                for (int q = 0; q < 4; q++) {
                    float e = __expf(S[ch][ms][q]);   // |s|<=1
                    S[ch][ms][q] = e; sum[ms][q] += e;
                }
        unsigned wA = g_maskbits[(size_t)nA * 64 + (m0 >> 5)];
        unsigned wB = g_maskbits[(size_t)(nA + 8) * 64 + (m0 >> 5)];
        float inv[2][4];
#pragma unroll
        for (int ms = 0; ms < 2; ms++)
#pragma unroll
            for (int q = 0; q < 4; q++) {
                int bitpos = mh * 16 + ms * 8 + 2 * tig + (q & 1);
                unsigned wd = (q >> 1) ? wB : wA;
                inv[ms][q] = ((wd >> bitpos) & 1u) ? __fdividef(1.f, sum[ms][q]) : 0.f;
            }
        uint32_t attH[8][4], attL[8][4];
#pragma unroll
        for (int ch = 0; ch < 8; ch++)
#pragma unroll
            for (int ms = 0; ms < 2; ms++) {
                splitpair(S[ch][ms][0] * inv[ms][0], S[ch][ms][1] * inv[ms][1],
                          attH[ch][ms * 2], attL[ch][ms * 2]);
                splitpair(S[ch][ms][2] * inv[ms][2], S[ch][ms][3] * inv[ms][3],
                          attH[ch][ms * 2 + 1], attL[ch][ms * 2 + 1]);
            }

        // ---- Phase B: C += att . Zm  (3-term split: aH.bH + aL.bH + aH.bL) ----
#pragma unroll
        for (int ch = 0; ch < 8; ch++) {
            uint32_t d0 = (uint32_t)(ch * 32) * 2, d1 = (uint32_t)(ch * 32 + 16) * 2;
            uint32_t bh0[4], bh1[4], bl0[4], bl1[4];
            LDSM4T(bh0, sb + bufc + boffT + d0);
            LDSM4T(bh1, sb + bufc + boffT + d1);
            LDSM4T(bl0, sb + bufc + ZMHALF + boffT + d0);
            LDSM4T(bl1, sb + bufc + ZMHALF + boffT + d1);
            MMA(C[ch][0], attH[ch], bh0[0], bh0[1]);
            MMA(C[ch][1], attH[ch], bh0[2], bh0[3]);
            MMA(C[ch][2], attH[ch], bh1[0], bh1[1]);
            MMA(C[ch][3], attH[ch], bh1[2], bh1[3]);
            MMA(C[ch][0], attL[ch], bh0[0], bh0[1]);
            MMA(C[ch][1], attL[ch], bh0[2], bh0[3]);
            MMA(C[ch][2], attL[ch], bh1[0], bh1[1]);
            MMA(C[ch][3], attL[ch], bh1[2], bh1[3]);
            MMA(C[ch][0], attH[ch], bl0[0], bl0[1]);
            MMA(C[ch][1], attH[ch], bl0[2], bl0[3]);
            MMA(C[ch][2], attH[ch], bl1[0], bl1[1]);
            MMA(C[ch][3], attH[ch], bl1[2], bl1[3]);
        }
        __syncthreads();
    }

    // ---- combine m-halves in smem, then write g_part ----
    float* comb = (float*)(smem + OFF_ZM);
    if (mh == 1) {
        int nl = nb * 16 + g;
#pragma unroll
        for (int ch = 0; ch < 8; ch++)
#pragma unroll
            for (int db = 0; db < 4; db++) {
                int d = ch * 32 + db * 8 + 2 * tig;
                *(float2*)&comb[(size_t)nl * CPAD + d]       = make_float2(C[ch][db][0], C[ch][db][1]);
                *(float2*)&comb[(size_t)(nl + 8) * CPAD + d] = make_float2(C[ch][db][2], C[ch][db][3]);
            }
    }
    __syncthreads();
    if (mh == 0) {
        int nl = nb * 16 + g;
        float* dst = g_part[blockIdx.y];
#pragma unroll
        for (int ch = 0; ch < 8; ch++)
#pragma unroll
            for (int db = 0; db < 4; db++) {
                int d = ch * 32 + db * 8 + 2 * tig;
                float2 o0 = *(float2*)&comb[(size_t)nl * CPAD + d];
                float2 o1 = *(float2*)&comb[(size_t)(nl + 8) * CPAD + d];
                *(float2*)&dst[(size_t)nA * CDIM + d] =
                    make_float2(C[ch][db][0] + o0.x, C[ch][db][1] + o0.y);
                *(float2*)&dst[(size_t)(nA + 8) * CDIM + d] =
                    make_float2(C[ch][db][2] + o1.x, C[ch][db][3] + o1.y);
            }
    }
}

// ---------------- residual + sum 8 partials + L2 norm ----------------
__global__ void norm_kernel(int zi, int zo, float* __restrict__ outp) {
    int n = blockIdx.x, t = threadIdx.x;
    size_t i = (size_t)n * CDIM + t;
    float v = g_Z[zi][i];
#pragma unroll
    for (int s = 0; s < MS; s++) v += g_part[s][i];
    float ss = v * v;
#pragma unroll
    for (int o = 16; o; o >>= 1) ss += __shfl_xor_sync(0xffffffffu, ss, o);
    float r = v / fmaxf(sqrtf(ss), 1e-12f);
    if (outp) outp[i] = r; else g_Z[zo][i] = r;
}

extern "C" void kernel_launch(void* const* d_in, const int* in_sizes, int n_in,
                              void* d_out, int out_size) {
    const int* adj = nullptr; const float* feat = nullptr;
    const float* W = nullptr; const float* b = nullptr;
    for (int i = 0; i < n_in; i++) {
        switch (in_sizes[i]) {
            case NN * NN:      adj  = (const int*)d_in[i];   break;
            case NN * 128:     feat = (const float*)d_in[i]; break;
            case 8 * 128 * 32: W    = (const float*)d_in[i]; break;
            case 256:          b    = (const float*)d_in[i]; break;
        }
    }
    float* out = (float*)d_out;

    cudaFuncSetAttribute(iter_kernel, cudaFuncAttributeMaxDynamicSharedMemorySize, SM_TOTAL);

    pack_mask_kernel<<<NN * (NN / 32) / 256, 256>>>(adj);
    proj_kernel<<<NN, 256>>>(feat, W, b);

    int cur = 0;
    for (int it = 0; it < 4; it++) {
        dim3 grid(NN / 64, MS);
        iter_kernel<<<grid, 256, SM_TOTAL>>>(cur);
        norm_kernel<<<NN, 256>>>(cur, cur ^ 1, (it == 3) ? out : nullptr);
        cur ^= 1;
    }
}

// round 9
// speedup vs baseline: 1.9096x; 1.0623x over previous
#include <cuda_runtime.h>
#include <cuda_fp16.h>
#include <cstdint>

#define NN   2048
#define CDIM 256
#define MS   8          // m splits (blockIdx.y)
#define PAD  264        // fp16 elems per smem row (padded)

__device__ float    g_Z[2][NN * CDIM];
__device__ float    g_part[MS][NN * CDIM];       // per m-split partials (halves combined)
__device__ unsigned g_maskbits[NN * (NN / 32)];  // word[n*64+mw], bit = m&31

// smem byte offsets
#define OFF_ZNH  0                               // Zn high only (single-term Phase A)
#define OFF_ZM   (64 * PAD * 2)                  // 33792; 2 buffers of (h|l)
#define ZMBUF    (2 * 32 * PAD * 2)              // 33792 per buffer (h then l)
#define ZMHALF   (32 * PAD * 2)                  // 16896
#define SM_TOTAL (OFF_ZM + 2 * ZMBUF)            // 101376
#define CPAD     264                             // combine-area row stride (floats)

__device__ __forceinline__ uint32_t smem_u32(const void* p) {
    uint32_t a;
    asm("{ .reg .u64 t; cvta.to.shared.u64 t, %1; cvt.u32.u64 %0, t; }" : "=r"(a) : "l"(p));
    return a;
}

// float pair -> packed fp16 (high part only)
__device__ __forceinline__ uint32_t packh(float x0, float x1) {
    __half2 hp = __floats2half2_rn(x0, x1);
    return *(uint32_t*)&hp;
}
// float pair -> fp16 high/low split, packed b32
__device__ __forceinline__ void splitpair(float x0, float x1, uint32_t& h, uint32_t& l) {
    __half h0 = __float2half_rn(x0), h1 = __float2half_rn(x1);
    float r0 = x0 - __half2float(h0), r1 = x1 - __half2float(h1);
    __half2 hp; hp.x = h0; hp.y = h1;
    __half2 lp = __floats2half2_rn(r0, r1);
    h = *(uint32_t*)&hp; l = *(uint32_t*)&lp;
}

#define LDSM4(r, a) asm volatile( \
    "ldmatrix.sync.aligned.m8n8.x4.shared.b16 {%0,%1,%2,%3}, [%4];" \
    : "=r"((r)[0]), "=r"((r)[1]), "=r"((r)[2]), "=r"((r)[3]) : "r"(a))
#define LDSM4T(r, a) asm volatile( \
    "ldmatrix.sync.aligned.m8n8.x4.trans.shared.b16 {%0,%1,%2,%3}, [%4];" \
    : "=r"((r)[0]), "=r"((r)[1]), "=r"((r)[2]), "=r"((r)[3]) : "r"(a))
#define MMA(d, a, b0, b1) asm volatile( \
    "mma.sync.aligned.m16n8k16.row.col.f32.f16.f16.f32 " \
    "{%0,%1,%2,%3}, {%4,%5,%6,%7}, {%8,%9}, {%0,%1,%2,%3};" \
    : "+f"((d)[0]), "+f"((d)[1]), "+f"((d)[2]), "+f"((d)[3]) \
    : "r"((a)[0]), "r"((a)[1]), "r"((a)[2]), "r"((a)[3]), "r"(b0), "r"(b1))

// ---------------- pack adjacency bits [n][mword] ----------------
__global__ void pack_mask_kernel(const int* __restrict__ adj) {
    int wIdx = blockIdx.x * 256 + threadIdx.x;
    const int4* p = ((const int4*)adj) + (size_t)wIdx * 8;
    unsigned bits = 0;
#pragma unroll
    for (int j = 0; j < 8; j++) {
        int4 v = p[j];
        if (v.x > 0) bits |= 1u << (4 * j + 0);
        if (v.y > 0) bits |= 1u << (4 * j + 1);
        if (v.z > 0) bits |= 1u << (4 * j + 2);
        if (v.w > 0) bits |= 1u << (4 * j + 3);
    }
    g_maskbits[wIdx] = bits;
}

// ---------------- projection + L2 norm ----------------
__global__ void proj_kernel(const float* __restrict__ feat,
                            const float* __restrict__ W,
                            const float* __restrict__ b) {
    __shared__ float fs[128];
    int n = blockIdx.x, t = threadIdx.x;
    if (t < 128) fs[t] = feat[n * 128 + t];
    __syncthreads();
    int k = t >> 5, d = t & 31;
    const float* Wp = W + k * 4096 + d;
    float s = b[t];
#pragma unroll 16
    for (int i = 0; i < 128; i++) s = fmaf(fs[i], Wp[i * 32], s);
    float ss = s * s;
#pragma unroll
    for (int o = 16; o; o >>= 1) ss += __shfl_xor_sync(0xffffffffu, ss, o);
    float inv = 1.0f / fmaxf(sqrtf(ss), 1e-12f);
    g_Z[0][(size_t)n * CDIM + t] = s * inv;
}

// ---------------- fused iteration (fp16 splits) ----------------
// block: 64 n x 256 m; 8 warps = 4 n-blocks(16) x 2 m-halves(128)
__global__ __launch_bounds__(256, 1) void iter_kernel(int zi) {
    extern __shared__ char smem[];
    const float* __restrict__ Z = g_Z[zi];
    uint32_t sb = smem_u32(smem);
    int t = threadIdx.x, w = t >> 5, lane = t & 31;
    int nb = w & 3, mh = w >> 2;
    int g = lane >> 2, tig = lane & 3;
    int n0 = blockIdx.x * 64, mbase = blockIdx.y * (NN / MS);

    // ---- fill Zn (64 x 256) fp16 high only ----
#pragma unroll 4
    for (int it = 0; it < 32; it++) {
        int idx = t + it * 256;
        int n = idx >> 7, cp = idx & 127;
        float2 v = *(const float2*)(Z + (size_t)(n0 + n) * CDIM + 2 * cp);
        uint32_t bo = (uint32_t)(n * PAD + 2 * cp) * 2;
        *(uint32_t*)(smem + OFF_ZNH + bo) = packh(v.x, v.y);
    }

    // fill Zm tile 0 into buffer 0 (h + l)
    {
#pragma unroll 2
        for (int it = 0; it < 16; it++) {
            int idx = t + it * 256;
            int m = idx >> 7, cp = idx & 127;
            float2 v = *(const float2*)(Z + (size_t)(mbase + m) * CDIM + 2 * cp);
            uint32_t h, l; splitpair(v.x, v.y, h, l);
            uint32_t bo = (uint32_t)(m * PAD + 2 * cp) * 2;
            *(uint32_t*)(smem + OFF_ZM + bo) = h;
            *(uint32_t*)(smem + OFF_ZM + ZMHALF + bo) = l;
        }
    }
    __syncthreads();

    uint32_t aoffA = (uint32_t)(((nb * 16 + (lane & 15)) * PAD + ((lane >> 4) << 3)) * 2);
    uint32_t boffA = (uint32_t)(((mh * 16 + ((lane >> 4) << 3) + (lane & 7)) * PAD +
                                 (((lane >> 3) & 1) << 3)) * 2);
    uint32_t boffT = (uint32_t)(((mh * 16 + (((lane >> 3) & 1) << 3) + (lane & 7)) * PAD +
                                 ((lane >> 4) << 3)) * 2);
    int nA = n0 + nb * 16 + g;

    float C[8][4][4];
#pragma unroll
    for (int c = 0; c < 8; c++)
#pragma unroll
        for (int q = 0; q < 4; q++) { C[c][q][0] = C[c][q][1] = C[c][q][2] = C[c][q][3] = 0.f; }

    for (int mt = 0; mt < 8; mt++) {
        int m0 = mbase + mt * 32;
        uint32_t bufc = OFF_ZM + (uint32_t)(mt & 1) * ZMBUF;

        // ---- prefetch next Zm tile into other buffer (overlaps compute) ----
        if (mt < 7) {
            uint32_t bufn = OFF_ZM + (uint32_t)((mt + 1) & 1) * ZMBUF;
            int m1 = m0 + 32;
#pragma unroll 2
            for (int it = 0; it < 16; it++) {
                int idx = t + it * 256;
                int m = idx >> 7, cp = idx & 127;
                float2 v = *(const float2*)(Z + (size_t)(m1 + m) * CDIM + 2 * cp);
                uint32_t h, l; splitpair(v.x, v.y, h, l);
                uint32_t bo = (uint32_t)(m * PAD + 2 * cp) * 2;
                *(uint32_t*)(smem + bufn + bo) = h;
                *(uint32_t*)(smem + bufn + ZMHALF + bo) = l;
            }
        }

        // ---- Phase A: S = ZnH . ZmH^T (single fp16 term; err ~2e-4) ----
        float S[8][2][4];
#pragma unroll
        for (int c = 0; c < 8; c++)
#pragma unroll
            for (int ms = 0; ms < 2; ms++) { S[c][ms][0] = S[c][ms][1] = S[c][ms][2] = S[c][ms][3] = 0.f; }
#pragma unroll
        for (int ch = 0; ch < 8; ch++) {
#pragma unroll
            for (int ks = 0; ks < 2; ks++) {
                uint32_t kb2 = (uint32_t)(ch * 32 + ks * 16) * 2;
                uint32_t aH[4], bH[4];
                LDSM4(aH, sb + OFF_ZNH + aoffA + kb2);
                LDSM4(bH, sb + bufc + boffA + kb2);
                MMA(S[ch][0], aH, bH[0], bH[1]);
                MMA(S[ch][1], aH, bH[2], bH[3]);
            }
        }

        // ---- softmax over channels (in-lane) ----
        float sum[2][4];
#pragma unroll
        for (int ms = 0; ms < 2; ms++)
#pragma unroll
            for (int q = 0; q < 4; q++) sum[ms][q] = 0.f;
#pragma unroll
        for (int ch = 0; ch < 8; ch++)
#pragma unroll
            for (int ms = 0; ms < 2; ms++)
#pragma unroll
                for (int q = 0; q < 4; q++) {
                    float e = __expf(S[ch][ms][q]);   // |s|<=1
                    S[ch][ms][q] = e; sum[ms][q] += e;
                }
        unsigned wA = g_maskbits[(size_t)nA * 64 + (m0 >> 5)];
        unsigned wB = g_maskbits[(size_t)(nA + 8) * 64 + (m0 >> 5)];
        float inv[2][4];
#pragma unroll
        for (int ms = 0; ms < 2; ms++)
#pragma unroll
            for (int q = 0; q < 4; q++) {
                int bitpos = mh * 16 + ms * 8 + 2 * tig + (q & 1);
                unsigned wd = (q >> 1) ? wB : wA;
                inv[ms][q] = ((wd >> bitpos) & 1u) ? __fdividef(1.f, sum[ms][q]) : 0.f;
            }
        uint32_t attH[8][4], attL[8][4];
#pragma unroll
        for (int ch = 0; ch < 8; ch++)
#pragma unroll
            for (int ms = 0; ms < 2; ms++) {
                splitpair(S[ch][ms][0] * inv[ms][0], S[ch][ms][1] * inv[ms][1],
                          attH[ch][ms * 2], attL[ch][ms * 2]);
                splitpair(S[ch][ms][2] * inv[ms][2], S[ch][ms][3] * inv[ms][3],
                          attH[ch][ms * 2 + 1], attL[ch][ms * 2 + 1]);
            }

        // ---- Phase B: C += att . Zm  (3-term fp16: aH.bH + aL.bH + aH.bL) ----
#pragma unroll
        for (int ch = 0; ch < 8; ch++) {
            uint32_t d0 = (uint32_t)(ch * 32) * 2, d1 = (uint32_t)(ch * 32 + 16) * 2;
            uint32_t bh0[4], bh1[4], bl0[4], bl1[4];
            LDSM4T(bh0, sb + bufc + boffT + d0);
            LDSM4T(bh1, sb + bufc + boffT + d1);
            LDSM4T(bl0, sb + bufc + ZMHALF + boffT + d0);
            LDSM4T(bl1, sb + bufc + ZMHALF + boffT + d1);
            MMA(C[ch][0], attH[ch], bh0[0], bh0[1]);
            MMA(C[ch][1], attH[ch], bh0[2], bh0[3]);
            MMA(C[ch][2], attH[ch], bh1[0], bh1[1]);
            MMA(C[ch][3], attH[ch], bh1[2], bh1[3]);
            MMA(C[ch][0], attL[ch], bh0[0], bh0[1]);
            MMA(C[ch][1], attL[ch], bh0[2], bh0[3]);
            MMA(C[ch][2], attL[ch], bh1[0], bh1[1]);
            MMA(C[ch][3], attL[ch], bh1[2], bh1[3]);
            MMA(C[ch][0], attH[ch], bl0[0], bl0[1]);
            MMA(C[ch][1], attH[ch], bl0[2], bl0[3]);
            MMA(C[ch][2], attH[ch], bl1[0], bl1[1]);
            MMA(C[ch][3], attH[ch], bl1[2], bl1[3]);
        }
        __syncthreads();
    }

    // ---- combine m-halves in smem, then write g_part ----
    float* comb = (float*)(smem + OFF_ZM);
    if (mh == 1) {
        int nl = nb * 16 + g;
#pragma unroll
        for (int ch = 0; ch < 8; ch++)
#pragma unroll
            for (int db = 0; db < 4; db++) {
                int d = ch * 32 + db * 8 + 2 * tig;
                *(float2*)&comb[(size_t)nl * CPAD + d]       = make_float2(C[ch][db][0], C[ch][db][1]);
                *(float2*)&comb[(size_t)(nl + 8) * CPAD + d] = make_float2(C[ch][db][2], C[ch][db][3]);
            }
    }
    __syncthreads();
    if (mh == 0) {
        int nl = nb * 16 + g;
        float* dst = g_part[blockIdx.y];
#pragma unroll
        for (int ch = 0; ch < 8; ch++)
#pragma unroll
            for (int db = 0; db < 4; db++) {
                int d = ch * 32 + db * 8 + 2 * tig;
                float2 o0 = *(float2*)&comb[(size_t)nl * CPAD + d];
                float2 o1 = *(float2*)&comb[(size_t)(nl + 8) * CPAD + d];
                *(float2*)&dst[(size_t)nA * CDIM + d] =
                    make_float2(C[ch][db][0] + o0.x, C[ch][db][1] + o0.y);
                *(float2*)&dst[(size_t)(nA + 8) * CDIM + d] =
                    make_float2(C[ch][db][2] + o1.x, C[ch][db][3] + o1.y);
            }
    }
}

// ---------------- residual + sum 8 partials + L2 norm ----------------
__global__ void norm_kernel(int zi, int zo, float* __restrict__ outp) {
    int n = blockIdx.x, t = threadIdx.x;
    size_t i = (size_t)n * CDIM + t;
    float v = g_Z[zi][i];
#pragma unroll
    for (int s = 0; s < MS; s++) v += g_part[s][i];
    float ss = v * v;
#pragma unroll
    for (int o = 16; o; o >>= 1) ss += __shfl_xor_sync(0xffffffffu, ss, o);
    float r = v / fmaxf(sqrtf(ss), 1e-12f);
    if (outp) outp[i] = r; else g_Z[zo][i] = r;
}

extern "C" void kernel_launch(void* const* d_in, const int* in_sizes, int n_in,
                              void* d_out, int out_size) {
    const int* adj = nullptr; const float* feat = nullptr;
    const float* W = nullptr; const float* b = nullptr;
    for (int i = 0; i < n_in; i++) {
        switch (in_sizes[i]) {
            case NN * NN:      adj  = (const int*)d_in[i];   break;
            case NN * 128:     feat = (const float*)d_in[i]; break;
            case 8 * 128 * 32: W    = (const float*)d_in[i]; break;
            case 256:          b    = (const float*)d_in[i]; break;
        }
    }
    float* out = (float*)d_out;

    cudaFuncSetAttribute(iter_kernel, cudaFuncAttributeMaxDynamicSharedMemorySize, SM_TOTAL);

    pack_mask_kernel<<<NN * (NN / 32) / 256, 256>>>(adj);
    proj_kernel<<<NN, 256>>>(feat, W, b);

    int cur = 0;
    for (int it = 0; it < 4; it++) {
        dim3 grid(NN / 64, MS);
        iter_kernel<<<grid, 256, SM_TOTAL>>>(cur);
        norm_kernel<<<NN, 256>>>(cur, cur ^ 1, (it == 3) ? out : nullptr);
        cur ^= 1;
    }
}

// round 10
// speedup vs baseline: 3.1119x; 1.6296x over previous
#include <cuda_runtime.h>
#include <cuda_fp16.h>
#include <cstdint>

#define NN   2048
#define CDIM 256
#define MS   8          // m splits (blockIdx.y)
#define PAD  264        // fp16 elems per smem row (padded); 528 B row stride

__device__ float    g_Z[2][NN * CDIM];
__device__ __half   g_Zh[NN * CDIM];             // fp16 high part of current Z
__device__ float    g_part[MS][NN * CDIM];       // per m-split partials
__device__ unsigned g_maskbits[NN * (NN / 32)];  // word[n*64+mw], bit = m&31

// smem layout (bytes)
#define OFF_ZN   0                               // Zn fp16-high: 64 x PAD
#define OFF_ZM   (64 * PAD * 2)                  // 33792; 2 buffers (h only)
#define ZMBUF    (32 * PAD * 2)                  // 16896
#define SM_TOTAL (OFF_ZM + 2 * ZMBUF)            // 67584
#define CPAD     264                             // combine-area stride (floats); 64*CPAD*4 = 67584

__device__ __forceinline__ uint32_t smem_u32(const void* p) {
    uint32_t a;
    asm("{ .reg .u64 t; cvta.to.shared.u64 t, %1; cvt.u32.u64 %0, t; }" : "=r"(a) : "l"(p));
    return a;
}
// float pair -> fp16 high/low split, packed b32
__device__ __forceinline__ void splitpair(float x0, float x1, uint32_t& h, uint32_t& l) {
    __half h0 = __float2half_rn(x0), h1 = __float2half_rn(x1);
    float r0 = x0 - __half2float(h0), r1 = x1 - __half2float(h1);
    __half2 hp; hp.x = h0; hp.y = h1;
    __half2 lp = __floats2half2_rn(r0, r1);
    h = *(uint32_t*)&hp; l = *(uint32_t*)&lp;
}

#define LDSM4(r, a) asm volatile( \
    "ldmatrix.sync.aligned.m8n8.x4.shared.b16 {%0,%1,%2,%3}, [%4];" \
    : "=r"((r)[0]), "=r"((r)[1]), "=r"((r)[2]), "=r"((r)[3]) : "r"(a))
#define LDSM4T(r, a) asm volatile( \
    "ldmatrix.sync.aligned.m8n8.x4.trans.shared.b16 {%0,%1,%2,%3}, [%4];" \
    : "=r"((r)[0]), "=r"((r)[1]), "=r"((r)[2]), "=r"((r)[3]) : "r"(a))
#define MMA(d, a, b0, b1) asm volatile( \
    "mma.sync.aligned.m16n8k16.row.col.f32.f16.f16.f32 " \
    "{%0,%1,%2,%3}, {%4,%5,%6,%7}, {%8,%9}, {%0,%1,%2,%3};" \
    : "+f"((d)[0]), "+f"((d)[1]), "+f"((d)[2]), "+f"((d)[3]) \
    : "r"((a)[0]), "r"((a)[1]), "r"((a)[2]), "r"((a)[3]), "r"(b0), "r"(b1))

// ---------------- pack adjacency bits [n][mword] ----------------
__global__ void pack_mask_kernel(const int* __restrict__ adj) {
    int wIdx = blockIdx.x * 256 + threadIdx.x;
    const int4* p = ((const int4*)adj) + (size_t)wIdx * 8;
    unsigned bits = 0;
#pragma unroll
    for (int j = 0; j < 8; j++) {
        int4 v = p[j];
        if (v.x > 0) bits |= 1u << (4 * j + 0);
        if (v.y > 0) bits |= 1u << (4 * j + 1);
        if (v.z > 0) bits |= 1u << (4 * j + 2);
        if (v.w > 0) bits |= 1u << (4 * j + 3);
    }
    g_maskbits[wIdx] = bits;
}

// ---------------- projection + L2 norm (also emits fp16 high) ----------------
__global__ void proj_kernel(const float* __restrict__ feat,
                            const float* __restrict__ W,
                            const float* __restrict__ b) {
    __shared__ float fs[128];
    int n = blockIdx.x, t = threadIdx.x;
    if (t < 128) fs[t] = feat[n * 128 + t];
    __syncthreads();
    int k = t >> 5, d = t & 31;
    const float* Wp = W + k * 4096 + d;
    float s = b[t];
#pragma unroll 16
    for (int i = 0; i < 128; i++) s = fmaf(fs[i], Wp[i * 32], s);
    float ss = s * s;
#pragma unroll
    for (int o = 16; o; o >>= 1) ss += __shfl_xor_sync(0xffffffffu, ss, o);
    float inv = 1.0f / fmaxf(sqrtf(ss), 1e-12f);
    float r = s * inv;
    g_Z[0][(size_t)n * CDIM + t] = r;
    g_Zh[(size_t)n * CDIM + t] = __float2half_rn(r);
}

// ---------------- fused iteration ----------------
// block: 64 n x 256 m; 8 warps = 4 n-blocks(16) x 2 m-halves(128)
__global__ __launch_bounds__(256, 1) void iter_kernel(int unused) {
    extern __shared__ char smem[];
    uint32_t sb = smem_u32(smem);
    int t = threadIdx.x, w = t >> 5, lane = t & 31;
    int nb = w & 3, mh = w >> 2;
    int g = lane >> 2, tig = lane & 3;
    int n0 = blockIdx.x * 64, mbase = blockIdx.y * (NN / MS);

    // ---- fill Zn (64 x 256 fp16) : pure uint4 copy ----
#pragma unroll
    for (int it = 0; it < 8; it++) {
        int idx = t + it * 256;                  // uint4 index over 2048
        int n = idx >> 5, c4 = idx & 31;
        uint4 v = ((const uint4*)(g_Zh + (size_t)(n0 + n) * CDIM))[c4];
        *(uint4*)(smem + OFF_ZN + n * (PAD * 2) + c4 * 16) = v;
    }
    // fill Zm tile 0 into buffer 0
#pragma unroll
    for (int it = 0; it < 4; it++) {
        int idx = t + it * 256;                  // uint4 index over 1024
        int m = idx >> 5, c4 = idx & 31;
        uint4 v = ((const uint4*)(g_Zh + (size_t)(mbase + m) * CDIM))[c4];
        *(uint4*)(smem + OFF_ZM + m * (PAD * 2) + c4 * 16) = v;
    }
    __syncthreads();

    uint32_t aoffA = (uint32_t)(((nb * 16 + (lane & 15)) * PAD + ((lane >> 4) << 3)) * 2);
    uint32_t boffA = (uint32_t)(((mh * 16 + ((lane >> 4) << 3) + (lane & 7)) * PAD +
                                 (((lane >> 3) & 1) << 3)) * 2);
    uint32_t boffT = (uint32_t)(((mh * 16 + (((lane >> 3) & 1) << 3) + (lane & 7)) * PAD +
                                 ((lane >> 4) << 3)) * 2);
    int nA = n0 + nb * 16 + g;

    float C[8][4][4];
#pragma unroll
    for (int c = 0; c < 8; c++)
#pragma unroll
        for (int q = 0; q < 4; q++) { C[c][q][0] = C[c][q][1] = C[c][q][2] = C[c][q][3] = 0.f; }

    for (int mt = 0; mt < 8; mt++) {
        int m0 = mbase + mt * 32;
        uint32_t bufc = OFF_ZM + (uint32_t)(mt & 1) * ZMBUF;

        // ---- prefetch next Zm tile (pure copy, overlaps compute) ----
        if (mt < 7) {
            uint32_t bufn = OFF_ZM + (uint32_t)((mt + 1) & 1) * ZMBUF;
            int m1 = m0 + 32;
#pragma unroll
            for (int it = 0; it < 4; it++) {
                int idx = t + it * 256;
                int m = idx >> 5, c4 = idx & 31;
                uint4 v = ((const uint4*)(g_Zh + (size_t)(m1 + m) * CDIM))[c4];
                *(uint4*)(smem + bufn + m * (PAD * 2) + c4 * 16) = v;
            }
        }

        // ---- Phase A: S = ZnH . ZmH^T (single fp16 term) ----
        float S[8][2][4];
#pragma unroll
        for (int c = 0; c < 8; c++)
#pragma unroll
            for (int ms = 0; ms < 2; ms++) { S[c][ms][0] = S[c][ms][1] = S[c][ms][2] = S[c][ms][3] = 0.f; }
#pragma unroll
        for (int ch = 0; ch < 8; ch++) {
#pragma unroll
            for (int ks = 0; ks < 2; ks++) {
                uint32_t kb2 = (uint32_t)(ch * 32 + ks * 16) * 2;
                uint32_t aH[4], bH[4];
                LDSM4(aH, sb + OFF_ZN + aoffA + kb2);
                LDSM4(bH, sb + bufc + boffA + kb2);
                MMA(S[ch][0], aH, bH[0], bH[1]);
                MMA(S[ch][1], aH, bH[2], bH[3]);
            }
        }

        // ---- softmax over channels (in-lane) ----
        float sum[2][4];
#pragma unroll
        for (int ms = 0; ms < 2; ms++)
#pragma unroll
            for (int q = 0; q < 4; q++) sum[ms][q] = 0.f;
#pragma unroll
        for (int ch = 0; ch < 8; ch++)
#pragma unroll
            for (int ms = 0; ms < 2; ms++)
#pragma unroll
                for (int q = 0; q < 4; q++) {
                    float e = __expf(S[ch][ms][q]);   // |s|<=1
                    S[ch][ms][q] = e; sum[ms][q] += e;
                }
        unsigned wA = g_maskbits[(size_t)nA * 64 + (m0 >> 5)];
        unsigned wB = g_maskbits[(size_t)(nA + 8) * 64 + (m0 >> 5)];
        float inv[2][4];
#pragma unroll
        for (int ms = 0; ms < 2; ms++)
#pragma unroll
            for (int q = 0; q < 4; q++) {
                int bitpos = mh * 16 + ms * 8 + 2 * tig + (q & 1);
                unsigned wd = (q >> 1) ? wB : wA;
                inv[ms][q] = ((wd >> bitpos) & 1u) ? __fdividef(1.f, sum[ms][q]) : 0.f;
            }
        uint32_t attH[8][4], attL[8][4];
#pragma unroll
        for (int ch = 0; ch < 8; ch++)
#pragma unroll
            for (int ms = 0; ms < 2; ms++) {
                splitpair(S[ch][ms][0] * inv[ms][0], S[ch][ms][1] * inv[ms][1],
                          attH[ch][ms * 2], attL[ch][ms * 2]);
                splitpair(S[ch][ms][2] * inv[ms][2], S[ch][ms][3] * inv[ms][3],
                          attH[ch][ms * 2 + 1], attL[ch][ms * 2 + 1]);
            }

        // ---- Phase B: C += (attH + attL) . ZmH ----
#pragma unroll
        for (int ch = 0; ch < 8; ch++) {
            uint32_t d0 = (uint32_t)(ch * 32) * 2, d1 = (uint32_t)(ch * 32 + 16) * 2;
            uint32_t bh0[4], bh1[4];
            LDSM4T(bh0, sb + bufc + boffT + d0);
            LDSM4T(bh1, sb + bufc + boffT + d1);
            MMA(C[ch][0], attH[ch], bh0[0], bh0[1]);
            MMA(C[ch][1], attH[ch], bh0[2], bh0[3]);
            MMA(C[ch][2], attH[ch], bh1[0], bh1[1]);
            MMA(C[ch][3], attH[ch], bh1[2], bh1[3]);
            MMA(C[ch][0], attL[ch], bh0[0], bh0[1]);
            MMA(C[ch][1], attL[ch], bh0[2], bh0[3]);
            MMA(C[ch][2], attL[ch], bh1[0], bh1[1]);
            MMA(C[ch][3], attL[ch], bh1[2], bh1[3]);
        }
        __syncthreads();
    }

    // ---- combine m-halves in smem (overlays dead tile buffers), write g_part ----
    float* comb = (float*)smem;
    if (mh == 1) {
        int nl = nb * 16 + g;
#pragma unroll
        for (int ch = 0; ch < 8; ch++)
#pragma unroll
            for (int db = 0; db < 4; db++) {
                int d = ch * 32 + db * 8 + 2 * tig;
                *(float2*)&comb[(size_t)nl * CPAD + d]       = make_float2(C[ch][db][0], C[ch][db][1]);
                *(float2*)&comb[(size_t)(nl + 8) * CPAD + d] = make_float2(C[ch][db][2], C[ch][db][3]);
            }
    }
    __syncthreads();
    if (mh == 0) {
        int nl = nb * 16 + g;
        float* dst = g_part[blockIdx.y];
#pragma unroll
        for (int ch = 0; ch < 8; ch++)
#pragma unroll
            for (int db = 0; db < 4; db++) {
                int d = ch * 32 + db * 8 + 2 * tig;
                float2 o0 = *(float2*)&comb[(size_t)nl * CPAD + d];
                float2 o1 = *(float2*)&comb[(size_t)(nl + 8) * CPAD + d];
                *(float2*)&dst[(size_t)nA * CDIM + d] =
                    make_float2(C[ch][db][0] + o0.x, C[ch][db][1] + o0.y);
                *(float2*)&dst[(size_t)(nA + 8) * CDIM + d] =
                    make_float2(C[ch][db][2] + o1.x, C[ch][db][3] + o1.y);
            }
    }
}

// ---------------- residual + sum 8 partials + L2 norm (+ fp16 emit) ----------------
__global__ void norm_kernel(int zi, int zo, float* __restrict__ outp) {
    int n = blockIdx.x, t = threadIdx.x;
    size_t i = (size_t)n * CDIM + t;
    float v = g_Z[zi][i];
#pragma unroll
    for (int s = 0; s < MS; s++) v += g_part[s][i];
    float ss = v * v;
#pragma unroll
    for (int o = 16; o; o >>= 1) ss += __shfl_xor_sync(0xffffffffu, ss, o);
    float r = v / fmaxf(sqrtf(ss), 1e-12f);
    if (outp) { outp[i] = r; }
    else {
        g_Z[zo][i] = r;
        g_Zh[i] = __float2half_rn(r);
    }
}

extern "C" void kernel_launch(void* const* d_in, const int* in_sizes, int n_in,
                              void* d_out, int out_size) {
    const int* adj = nullptr; const float* feat = nullptr;
    const float* W = nullptr; const float* b = nullptr;
    for (int i = 0; i < n_in; i++) {
        switch (in_sizes[i]) {
            case NN * NN:      adj  = (const int*)d_in[i];   break;
            case NN * 128:     feat = (const float*)d_in[i]; break;
            case 8 * 128 * 32: W    = (const float*)d_in[i]; break;
            case 256:          b    = (const float*)d_in[i]; break;
        }
    }
    float* out = (float*)d_out;

    cudaFuncSetAttribute(iter_kernel, cudaFuncAttributeMaxDynamicSharedMemorySize, SM_TOTAL);

    pack_mask_kernel<<<NN * (NN / 32) / 256, 256>>>(adj);
    proj_kernel<<<NN, 256>>>(feat, W, b);

    int cur = 0;
    for (int it = 0; it < 4; it++) {
        dim3 grid(NN / 64, MS);
        iter_kernel<<<grid, 256, SM_TOTAL>>>(0);
        norm_kernel<<<NN, 256>>>(cur, cur ^ 1, (it == 3) ? out : nullptr);
        cur ^= 1;
    }
}

// round 11
// speedup vs baseline: 3.7140x; 1.1935x over previous
#include <cuda_runtime.h>
#include <cuda_fp16.h>
#include <cstdint>

#define NN   2048
#define CDIM 256
#define MS   8          // m splits (blockIdx.y)
#define PAD  264        // fp16 elems per smem row (padded); 528 B row stride

__device__ float    g_Z[2][NN * CDIM];
__device__ __half   g_Zh[NN * CDIM];             // fp16 high part of current Z
__device__ float    g_part[MS][NN * CDIM];       // per m-split partials
__device__ unsigned g_maskbits[NN * (NN / 32)];  // word[n*64+mw], bit = m&31

// smem layout (bytes): block = 32n x 256m
#define OFF_ZN   0                               // Zn fp16: 32 x PAD
#define OFF_ZM   (32 * PAD * 2)                  // 16896; 2 buffers
#define ZMBUF    (32 * PAD * 2)                  // 16896
#define SM_TOTAL (OFF_ZM + 2 * ZMBUF)            // 50688
#define CPAD     264                             // combine stride (floats); 32*CPAD*4 = 33792 <= SM_TOTAL

__device__ __forceinline__ uint32_t smem_u32(const void* p) {
    uint32_t a;
    asm("{ .reg .u64 t; cvta.to.shared.u64 t, %1; cvt.u32.u64 %0, t; }" : "=r"(a) : "l"(p));
    return a;
}
__device__ __forceinline__ uint32_t packh(float x0, float x1) {
    __half2 hp = __floats2half2_rn(x0, x1);
    return *(uint32_t*)&hp;
}

#define LDSM4(r, a) asm volatile( \
    "ldmatrix.sync.aligned.m8n8.x4.shared.b16 {%0,%1,%2,%3}, [%4];" \
    : "=r"((r)[0]), "=r"((r)[1]), "=r"((r)[2]), "=r"((r)[3]) : "r"(a))
#define LDSM4T(r, a) asm volatile( \
    "ldmatrix.sync.aligned.m8n8.x4.trans.shared.b16 {%0,%1,%2,%3}, [%4];" \
    : "=r"((r)[0]), "=r"((r)[1]), "=r"((r)[2]), "=r"((r)[3]) : "r"(a))
#define MMA(d, a, b0, b1) asm volatile( \
    "mma.sync.aligned.m16n8k16.row.col.f32.f16.f16.f32 " \
    "{%0,%1,%2,%3}, {%4,%5,%6,%7}, {%8,%9}, {%0,%1,%2,%3};" \
    : "+f"((d)[0]), "+f"((d)[1]), "+f"((d)[2]), "+f"((d)[3]) \
    : "r"((a)[0]), "r"((a)[1]), "r"((a)[2]), "r"((a)[3]), "r"(b0), "r"(b1))

// ---------------- pack adjacency bits [n][mword] ----------------
__global__ void pack_mask_kernel(const int* __restrict__ adj) {
    int wIdx = blockIdx.x * 256 + threadIdx.x;
    const int4* p = ((const int4*)adj) + (size_t)wIdx * 8;
    unsigned bits = 0;
#pragma unroll
    for (int j = 0; j < 8; j++) {
        int4 v = p[j];
        if (v.x > 0) bits |= 1u << (4 * j + 0);
        if (v.y > 0) bits |= 1u << (4 * j + 1);
        if (v.z > 0) bits |= 1u << (4 * j + 2);
        if (v.w > 0) bits |= 1u << (4 * j + 3);
    }
    g_maskbits[wIdx] = bits;
}

// ---------------- projection + L2 norm (emits fp32 + fp16) ----------------
__global__ void proj_kernel(const float* __restrict__ feat,
                            const float* __restrict__ W,
                            const float* __restrict__ b) {
    __shared__ float fs[128];
    int n = blockIdx.x, t = threadIdx.x;
    if (t < 128) fs[t] = feat[n * 128 + t];
    __syncthreads();
    int k = t >> 5, d = t & 31;
    const float* Wp = W + k * 4096 + d;
    float s = b[t];
#pragma unroll 16
    for (int i = 0; i < 128; i++) s = fmaf(fs[i], Wp[i * 32], s);
    float ss = s * s;
#pragma unroll
    for (int o = 16; o; o >>= 1) ss += __shfl_xor_sync(0xffffffffu, ss, o);
    float inv = 1.0f / fmaxf(sqrtf(ss), 1e-12f);
    float r = s * inv;
    g_Z[0][(size_t)n * CDIM + t] = r;
    g_Zh[(size_t)n * CDIM + t] = __float2half_rn(r);
}

// ---------------- fused iteration ----------------
// block: 32 n x 256 m; 4 warps = 2 n-blocks(16) x 2 m-halves(128); 2 blocks/SM
__global__ __launch_bounds__(128, 2) void iter_kernel(int unused) {
    extern __shared__ char smem[];
    uint32_t sb = smem_u32(smem);
    int t = threadIdx.x, w = t >> 5, lane = t & 31;
    int nb = w & 1, mh = w >> 1;
    int g = lane >> 2, tig = lane & 3;
    int n0 = blockIdx.x * 32, mbase = blockIdx.y * (NN / MS);

    // ---- fill Zn (32 x 256 fp16): pure uint4 copy ----
#pragma unroll
    for (int it = 0; it < 8; it++) {
        int idx = t + it * 128;                  // uint4 index over 1024
        int n = idx >> 5, c4 = idx & 31;
        uint4 v = ((const uint4*)(g_Zh + (size_t)(n0 + n) * CDIM))[c4];
        *(uint4*)(smem + OFF_ZN + n * (PAD * 2) + c4 * 16) = v;
    }
    // fill Zm tile 0 into buffer 0
#pragma unroll
    for (int it = 0; it < 8; it++) {
        int idx = t + it * 128;
        int m = idx >> 5, c4 = idx & 31;
        uint4 v = ((const uint4*)(g_Zh + (size_t)(mbase + m) * CDIM))[c4];
        *(uint4*)(smem + OFF_ZM + m * (PAD * 2) + c4 * 16) = v;
    }
    __syncthreads();

    uint32_t aoffA = (uint32_t)(((nb * 16 + (lane & 15)) * PAD + ((lane >> 4) << 3)) * 2);
    uint32_t boffA = (uint32_t)(((mh * 16 + ((lane >> 4) << 3) + (lane & 7)) * PAD +
                                 (((lane >> 3) & 1) << 3)) * 2);
    uint32_t boffT = (uint32_t)(((mh * 16 + (((lane >> 3) & 1) << 3) + (lane & 7)) * PAD +
                                 ((lane >> 4) << 3)) * 2);
    int nA = n0 + nb * 16 + g;

    float C[8][4][4];
#pragma unroll
    for (int c = 0; c < 8; c++)
#pragma unroll
        for (int q = 0; q < 4; q++) { C[c][q][0] = C[c][q][1] = C[c][q][2] = C[c][q][3] = 0.f; }

    for (int mt = 0; mt < 8; mt++) {
        int m0 = mbase + mt * 32;
        uint32_t bufc = OFF_ZM + (uint32_t)(mt & 1) * ZMBUF;

        // ---- prefetch next Zm tile (pure copy, overlaps compute) ----
        if (mt < 7) {
            uint32_t bufn = OFF_ZM + (uint32_t)((mt + 1) & 1) * ZMBUF;
            int m1 = m0 + 32;
#pragma unroll
            for (int it = 0; it < 8; it++) {
                int idx = t + it * 128;
                int m = idx >> 5, c4 = idx & 31;
                uint4 v = ((const uint4*)(g_Zh + (size_t)(m1 + m) * CDIM))[c4];
                *(uint4*)(smem + bufn + m * (PAD * 2) + c4 * 16) = v;
            }
        }

        // ---- Phase A: S = ZnH . ZmH^T (single fp16 term) ----
        float S[8][2][4];
#pragma unroll
        for (int c = 0; c < 8; c++)
#pragma unroll
            for (int ms = 0; ms < 2; ms++) { S[c][ms][0] = S[c][ms][1] = S[c][ms][2] = S[c][ms][3] = 0.f; }
#pragma unroll
        for (int ch = 0; ch < 8; ch++) {
#pragma unroll
            for (int ks = 0; ks < 2; ks++) {
                uint32_t kb2 = (uint32_t)(ch * 32 + ks * 16) * 2;
                uint32_t aH[4], bH[4];
                LDSM4(aH, sb + OFF_ZN + aoffA + kb2);
                LDSM4(bH, sb + bufc + boffA + kb2);
                MMA(S[ch][0], aH, bH[0], bH[1]);
                MMA(S[ch][1], aH, bH[2], bH[3]);
            }
        }

        // ---- softmax over channels (in-lane) ----
        float sum[2][4];
#pragma unroll
        for (int ms = 0; ms < 2; ms++)
#pragma unroll
            for (int q = 0; q < 4; q++) sum[ms][q] = 0.f;
#pragma unroll
        for (int ch = 0; ch < 8; ch++)
#pragma unroll
            for (int ms = 0; ms < 2; ms++)
#pragma unroll
                for (int q = 0; q < 4; q++) {
                    float e = __expf(S[ch][ms][q]);   // |s|<=1
                    S[ch][ms][q] = e; sum[ms][q] += e;
                }
        unsigned wA = g_maskbits[(size_t)nA * 64 + (m0 >> 5)];
        unsigned wB = g_maskbits[(size_t)(nA + 8) * 64 + (m0 >> 5)];
        float inv[2][4];
#pragma unroll
        for (int ms = 0; ms < 2; ms++)
#pragma unroll
            for (int q = 0; q < 4; q++) {
                int bitpos = mh * 16 + ms * 8 + 2 * tig + (q & 1);
                unsigned wd = (q >> 1) ? wB : wA;
                inv[ms][q] = ((wd >> bitpos) & 1u) ? __fdividef(1.f, sum[ms][q]) : 0.f;
            }
        uint32_t attH[8][4];
#pragma unroll
        for (int ch = 0; ch < 8; ch++)
#pragma unroll
            for (int ms = 0; ms < 2; ms++) {
                attH[ch][ms * 2]     = packh(S[ch][ms][0] * inv[ms][0], S[ch][ms][1] * inv[ms][1]);
                attH[ch][ms * 2 + 1] = packh(S[ch][ms][2] * inv[ms][2], S[ch][ms][3] * inv[ms][3]);
            }

        // ---- Phase B: C += attH . ZmH (single term) ----
#pragma unroll
        for (int ch = 0; ch < 8; ch++) {
            uint32_t d0 = (uint32_t)(ch * 32) * 2, d1 = (uint32_t)(ch * 32 + 16) * 2;
            uint32_t bh0[4], bh1[4];
            LDSM4T(bh0, sb + bufc + boffT + d0);
            LDSM4T(bh1, sb + bufc + boffT + d1);
            MMA(C[ch][0], attH[ch], bh0[0], bh0[1]);
            MMA(C[ch][1], attH[ch], bh0[2], bh0[3]);
            MMA(C[ch][2], attH[ch], bh1[0], bh1[1]);
            MMA(C[ch][3], attH[ch], bh1[2], bh1[3]);
        }
        __syncthreads();
    }

    // ---- combine m-halves in smem (overlays dead buffers), write g_part ----
    float* comb = (float*)smem;
    if (mh == 1) {
        int nl = nb * 16 + g;
#pragma unroll
        for (int ch = 0; ch < 8; ch++)
#pragma unroll
            for (int db = 0; db < 4; db++) {
                int d = ch * 32 + db * 8 + 2 * tig;
                *(float2*)&comb[(size_t)nl * CPAD + d]       = make_float2(C[ch][db][0], C[ch][db][1]);
                *(float2*)&comb[(size_t)(nl + 8) * CPAD + d] = make_float2(C[ch][db][2], C[ch][db][3]);
            }
    }
    __syncthreads();
    if (mh == 0) {
        int nl = nb * 16 + g;
        float* dst = g_part[blockIdx.y];
#pragma unroll
        for (int ch = 0; ch < 8; ch++)
#pragma unroll
            for (int db = 0; db < 4; db++) {
                int d = ch * 32 + db * 8 + 2 * tig;
                float2 o0 = *(float2*)&comb[(size_t)nl * CPAD + d];
                float2 o1 = *(float2*)&comb[(size_t)(nl + 8) * CPAD + d];
                *(float2*)&dst[(size_t)nA * CDIM + d] =
                    make_float2(C[ch][db][0] + o0.x, C[ch][db][1] + o0.y);
                *(float2*)&dst[(size_t)(nA + 8) * CDIM + d] =
                    make_float2(C[ch][db][2] + o1.x, C[ch][db][3] + o1.y);
            }
    }
}

// ---------------- residual + sum 8 partials + L2 norm (+ fp16 emit) ----------------
__global__ void norm_kernel(int zi, int zo, float* __restrict__ outp) {
    int n = blockIdx.x, t = threadIdx.x;
    size_t i = (size_t)n * CDIM + t;
    float v = g_Z[zi][i];
#pragma unroll
    for (int s = 0; s < MS; s++) v += g_part[s][i];
    float ss = v * v;
#pragma unroll
    for (int o = 16; o; o >>= 1) ss += __shfl_xor_sync(0xffffffffu, ss, o);
    float r = v / fmaxf(sqrtf(ss), 1e-12f);
    if (outp) { outp[i] = r; }
    else {
        g_Z[zo][i] = r;
        g_Zh[i] = __float2half_rn(r);
    }
}

extern "C" void kernel_launch(void* const* d_in, const int* in_sizes, int n_in,
                              void* d_out, int out_size) {
    const int* adj = nullptr; const float* feat = nullptr;
    const float* W = nullptr; const float* b = nullptr;
    for (int i = 0; i < n_in; i++) {
        switch (in_sizes[i]) {
            case NN * NN:      adj  = (const int*)d_in[i];   break;
            case NN * 128:     feat = (const float*)d_in[i]; break;
            case 8 * 128 * 32: W    = (const float*)d_in[i]; break;
            case 256:          b    = (const float*)d_in[i]; break;
        }
    }
    float* out = (float*)d_out;

    cudaFuncSetAttribute(iter_kernel, cudaFuncAttributeMaxDynamicSharedMemorySize, SM_TOTAL);

    pack_mask_kernel<<<NN * (NN / 32) / 256, 256>>>(adj);
    proj_kernel<<<NN, 256>>>(feat, W, b);

    int cur = 0;
    for (int it = 0; it < 4; it++) {
        dim3 grid(NN / 32, MS);
        iter_kernel<<<grid, 128, SM_TOTAL>>>(0);
        norm_kernel<<<NN, 256>>>(cur, cur ^ 1, (it == 3) ? out : nullptr);
        cur ^= 1;
    }
}